// round 5
// baseline (speedup 1.0000x reference)
#include <cuda_runtime.h>
#include <math.h>

#define N_NODES 40000
#define N_EDGES 640000
#define HID     128
#define NH      (N_NODES * HID)
#define NPAD    40960   // 1024 threads * 40 in scan

typedef unsigned long long u64;

// ---------------- device scratch (no allocations allowed) ----------------
__device__ __align__(16) float g_xproj[NH];
__device__ __align__(16) float g_stateA[NH];
__device__ __align__(16) float g_stateB[NH];
__device__ __align__(16) float g_aggr[NH];
__device__ __align__(16) float g_wt[HID * HID];
__device__ int   g_rowptr[N_NODES + 1];
__device__ int   g_cursor[N_NODES];
__device__ __align__(16) int g_counts[NPAD];
__device__ int   g_col[N_EDGES];
__device__ int   g_is64;

// ---------------- packed f32x2 helpers (B300 FFMA2 path) ----------------
__device__ __forceinline__ void fma2(u64& d, u64 a, u64 b) {
    asm("fma.rn.f32x2 %0, %1, %2, %3;" : "=l"(d) : "l"(a), "l"(b), "l"(d));
}
__device__ __forceinline__ float2 unpack2(u64 v) {
    float2 f; asm("mov.b64 {%0,%1}, %2;" : "=f"(f.x), "=f"(f.y) : "l"(v)); return f;
}

// ---------------- edge dtype probe: int64 vs int32 ----------------
__global__ void detect_kernel(const void* ei) {
    if (threadIdx.x == 0 && blockIdx.x == 0) {
        const long long* p = (const long long*)ei;
        int ok64 = 1;
        for (int i = 0; i < 64; i++) {
            long long v = p[(i * 9973) % 640000];
            if (v < 0 || v >= N_NODES) { ok64 = 0; break; }
        }
        g_is64 = ok64;
    }
}

__device__ __forceinline__ int edge_val(const void* ei, int idx) {
    int v;
    if (g_is64) v = (int)((const long long*)ei)[idx];
    else        v = ((const int*)ei)[idx];
    return ((unsigned)v < N_NODES) ? v : 0;   // clamp: never trap
}

// ---------------- CSR build ----------------
__global__ void zero_counts_kernel() {
    for (int i = blockIdx.x * blockDim.x + threadIdx.x; i < NPAD;
         i += gridDim.x * blockDim.x)
        g_counts[i] = 0;
}

__global__ void hist_kernel(const void* __restrict__ ei) {
    int e = blockIdx.x * blockDim.x + threadIdx.x;
    if (e < N_EDGES) {
        int dst = edge_val(ei, N_EDGES + e);
        atomicAdd(&g_counts[dst], 1);
    }
}

// single-block scan: 1024 threads x 40 elements via int4, shuffle scans
__global__ void scan_kernel() {
    __shared__ int wsum[32];
    int t = threadIdx.x, lane = t & 31, wid = t >> 5;
    const int4* c4 = (const int4*)g_counts;
    int base4 = t * 10;                 // 10 int4 = 40 ints per thread
    int s = 0;
#pragma unroll
    for (int j = 0; j < 10; j++) {
        int4 v = c4[base4 + j];
        s += v.x + v.y + v.z + v.w;
    }
    int v = s;
    for (int o = 1; o < 32; o <<= 1) {
        int n = __shfl_up_sync(0xffffffffu, v, o);
        if (lane >= o) v += n;
    }
    if (lane == 31) wsum[wid] = v;
    __syncthreads();
    if (wid == 0) {
        int w = wsum[lane];
        int vv = w;
        for (int o = 1; o < 32; o <<= 1) {
            int n = __shfl_up_sync(0xffffffffu, vv, o);
            if (lane >= o) vv += n;
        }
        wsum[lane] = vv - w;   // exclusive warp offsets
    }
    __syncthreads();
    int run = wsum[wid] + (v - s);   // exclusive prefix at this thread's chunk
#pragma unroll
    for (int j = 0; j < 10; j++) {
        int4 c = c4[base4 + j];
        int i = t * 40 + j * 4;
        if (i < N_NODES)     { g_cursor[i]   = run; run += c.x; g_rowptr[i + 1] = run; }
        if (i + 1 < N_NODES) { g_cursor[i+1] = run; run += c.y; g_rowptr[i + 2] = run; }
        if (i + 2 < N_NODES) { g_cursor[i+2] = run; run += c.z; g_rowptr[i + 3] = run; }
        if (i + 3 < N_NODES) { g_cursor[i+3] = run; run += c.w; g_rowptr[i + 4] = run; }
    }
    if (t == 0) g_rowptr[0] = 0;
}

__global__ void fill_kernel(const void* __restrict__ ei) {
    int e = blockIdx.x * blockDim.x + threadIdx.x;
    if (e < N_EDGES) {
        int src = edge_val(ei, e);
        int dst = edge_val(ei, N_EDGES + e);
        int pos = atomicAdd(&g_cursor[dst], 1);
        if ((unsigned)pos < N_EDGES) g_col[pos] = src;
    }
}

// ---------------- edge aggregation: warp per node, float4 lanes ----------------
// src_sel: 0 = stateA, 1 = stateB
__global__ void __launch_bounds__(256) aggregate_kernel(int src_sel) {
    int node = blockIdx.x * 8 + (threadIdx.x >> 5);
    if (node >= N_NODES) return;
    int lane = threadIdx.x & 31;
    int s = g_rowptr[node];
    int e = g_rowptr[node + 1];
    const float4* st = (const float4*)(src_sel ? g_stateB : g_stateA);
    float4 acc = make_float4(0.f, 0.f, 0.f, 0.f);
    for (int i = s; i < e; i++) {
        float4 v = st[g_col[i] * 32 + lane];
        acc.x += v.x; acc.y += v.y; acc.z += v.z; acc.w += v.w;
    }
    ((float4*)g_aggr)[node * 32 + lane] = acc;
}

// ---------------- transpose 128x128 into g_wt: wt[k][h] = w[h][k] ----------------
__global__ void transpose128_kernel(const float* __restrict__ w) {
    int idx = blockIdx.x * blockDim.x + threadIdx.x;
    if (idx < HID * HID) {
        int h = idx >> 7, k = idx & 127;
        g_wt[k * HID + h] = w[h * HID + k];
    }
}

// ---------------- first state update: stateA = tanh(xproj) ----------------
__global__ void tanh_kernel() {
    int i = blockIdx.x * blockDim.x + threadIdx.x;
    if (i < NH) g_stateA[i] = tanhf(g_xproj[i]);
}

// ---------------- FFMA2 GEMM ----------------------------------------------------
// dst[r][h] = f(bias? xproj + sum_k A[r][k] * W[k][h])
// 256 threads, 64 rows/block, thread tile 4 rows x 8 cols.
// Row-pairs packed in f32x2 (free via LDS.64 from k-major sA tile);
// W duplicated in smem as (w,w) so the inner loop is pure FFMA2 + loads.
#define GR   64
#define KT   16
#define APAD 66   // even (LDS.64 alignment), conflict-free

// a_sel: 0 = Aext, 1 = g_stateA, 2 = g_aggr
// W: Wext if non-null else g_wt
// dst_sel: 0 = g_stateA, 1 = g_stateB, 2 = dst_ext, 3 = g_xproj
__global__ void __launch_bounds__(256) gemm_kernel(
    const float* __restrict__ Aext, int a_sel,
    const float* __restrict__ Wext,
    int use_bias, int dst_sel, float* __restrict__ dst_ext, int do_tanh)
{
    __shared__ float2 sWd[KT * HID];   // duplicated W: [kk][h] = (w,w)   16 KB
    __shared__ float  sA[KT * APAD];   // k-major A tile: [kk][r]          4.2 KB

    const float* A = (a_sel == 0) ? Aext : ((a_sel == 1) ? g_stateA : g_aggr);
    const float* W = Wext ? Wext : g_wt;
    float* dst = (dst_sel == 0) ? g_stateA :
                 (dst_sel == 1) ? g_stateB :
                 (dst_sel == 2) ? dst_ext  : g_xproj;

    int t = threadIdx.x;
    int row0 = blockIdx.x * GR;
    int tc = t & 15;    // cols tc*8 .. +7
    int tr = t >> 4;    // rows tr*4 .. +3

    u64 acc[2][8];      // [rowpair][col]; pair p = rows (tr*4+2p, tr*4+2p+1)
#pragma unroll
    for (int p = 0; p < 2; p++)
#pragma unroll
        for (int j = 0; j < 8; j++) acc[p][j] = 0ull;

    for (int k0 = 0; k0 < HID; k0 += KT) {
        // W tile, duplicated: 2048 floats; thread reads strided scalars (coalesced)
#pragma unroll
        for (int j = 0; j < 8; j++) {
            int idx = t + j * 256;             // 0..2047
            float wv = W[k0 * HID + idx];
            sWd[idx] = make_float2(wv, wv);
        }
        // A tile transposed: 64 r x 16 k = 256 float4, one per thread
        {
            int r  = t >> 2;                   // 0..63
            int k4 = t & 3;                    // 0..3
            float4 v = *(const float4*)&A[(row0 + r) * HID + k0 + k4 * 4];
            sA[(k4 * 4 + 0) * APAD + r] = v.x;
            sA[(k4 * 4 + 1) * APAD + r] = v.y;
            sA[(k4 * 4 + 2) * APAD + r] = v.z;
            sA[(k4 * 4 + 3) * APAD + r] = v.w;
        }
        __syncthreads();

#pragma unroll
        for (int kk = 0; kk < KT; kk++) {
            const u64* wrow = (const u64*)&sWd[kk * HID + tc * 8];
            ulonglong2 w01 = *(const ulonglong2*)(wrow + 0);
            ulonglong2 w23 = *(const ulonglong2*)(wrow + 2);
            ulonglong2 w45 = *(const ulonglong2*)(wrow + 4);
            ulonglong2 w67 = *(const ulonglong2*)(wrow + 6);
            u64 a01 = *(const u64*)&sA[kk * APAD + tr * 4];
            u64 a23 = *(const u64*)&sA[kk * APAD + tr * 4 + 2];
            fma2(acc[0][0], a01, w01.x); fma2(acc[0][1], a01, w01.y);
            fma2(acc[0][2], a01, w23.x); fma2(acc[0][3], a01, w23.y);
            fma2(acc[0][4], a01, w45.x); fma2(acc[0][5], a01, w45.y);
            fma2(acc[0][6], a01, w67.x); fma2(acc[0][7], a01, w67.y);
            fma2(acc[1][0], a23, w01.x); fma2(acc[1][1], a23, w01.y);
            fma2(acc[1][2], a23, w23.x); fma2(acc[1][3], a23, w23.y);
            fma2(acc[1][4], a23, w45.x); fma2(acc[1][5], a23, w45.y);
            fma2(acc[1][6], a23, w67.x); fma2(acc[1][7], a23, w67.y);
        }
        __syncthreads();
    }

    // epilogue: pair p holds rows (tr*4+2p) in .lo and (tr*4+2p+1) in .hi
#pragma unroll
    for (int p = 0; p < 2; p++) {
        float v0[8], v1[8];
#pragma unroll
        for (int j = 0; j < 8; j++) {
            float2 q = unpack2(acc[p][j]);
            v0[j] = q.x; v1[j] = q.y;
        }
        int r0 = row0 + tr * 4 + 2 * p;
#pragma unroll
        for (int hrow = 0; hrow < 2; hrow++) {
            float* v = hrow ? v1 : v0;
            int r = r0 + hrow;
            if (use_bias) {
                float4 b0 = *(const float4*)&g_xproj[r * HID + tc * 8];
                float4 b1 = *(const float4*)&g_xproj[r * HID + tc * 8 + 4];
                v[0] += b0.x; v[1] += b0.y; v[2] += b0.z; v[3] += b0.w;
                v[4] += b1.x; v[5] += b1.y; v[6] += b1.z; v[7] += b1.w;
            }
            if (do_tanh) {
#pragma unroll
                for (int j = 0; j < 8; j++) v[j] = tanhf(v[j]);
            }
            *(float4*)&dst[r * HID + tc * 8]     = make_float4(v[0], v[1], v[2], v[3]);
            *(float4*)&dst[r * HID + tc * 8 + 4] = make_float4(v[4], v[5], v[6], v[7]);
        }
    }
}

// ---------------- host orchestration ----------------
extern "C" void kernel_launch(void* const* d_in, const int* in_sizes, int n_in,
                              void* d_out, int out_size)
{
    // Discover inputs by element count (robust to ordering):
    const void* ei = nullptr;
    const float* x = nullptr;
    const float* w[4] = {nullptr, nullptr, nullptr, nullptr};
    int wn = 0;
    for (int i = 0; i < n_in; i++) {
        if (in_sizes[i] == 2 * N_EDGES)      ei = d_in[i];
        else if (in_sizes[i] == NH)          x  = (const float*)d_in[i];
        else if (in_sizes[i] == HID * HID && wn < 4) w[wn++] = (const float*)d_in[i];
    }
    const float* w_in0  = w[0];
    const float* w_rec0 = w[1];
    const float* w_in1  = w[2];
    const float* w_rec1 = w[3];
    float* out = (float*)d_out;

    // Build dst-major CSR once per launch
    detect_kernel<<<1, 32>>>(ei);
    zero_counts_kernel<<<40, 1024>>>();
    hist_kernel<<<(N_EDGES + 255) / 256, 256>>>(ei);
    scan_kernel<<<1, 1024>>>();
    fill_kernel<<<(N_EDGES + 255) / 256, 256>>>(ei);

    const int BLOCKS = N_NODES / GR;             // 625
    const int TANH_BLOCKS = (NH + 255) / 256;
    const int AGGR_BLOCKS = (N_NODES + 7) / 8;   // 5000

    for (int layer = 0; layer < 2; layer++) {
        const float* win  = layer ? w_in1  : w_in0;
        const float* wrec = layer ? w_rec1 : w_rec0;

        // xproj = input @ win^T
        transpose128_kernel<<<64, 256>>>(win);
        gemm_kernel<<<BLOCKS, 256>>>(
            layer ? nullptr : x, layer ? 1 : 0,   // A = x or stateA
            nullptr,                              // W = g_wt (transposed)
            0, /*dst=xproj*/ 3, nullptr, 0);

        // state update #1 (initial state zero): stateA = tanh(xproj)
        tanh_kernel<<<TANH_BLOCKS, 256>>>();

        // 8 more updates: state = tanh(xproj + aggr(state) @ wrec)
        // ping-pong A->B->A->... (ends back in A after 8 iterations)
        for (int it = 0; it < 8; it++) {
            int src = it & 1;            // 0=A,1=B
            aggregate_kernel<<<AGGR_BLOCKS, 256>>>(src);
            int last = (layer == 1 && it == 7);
            int dst = last ? 2 : (1 - src);
            gemm_kernel<<<BLOCKS, 256>>>(
                nullptr, /*A=g_aggr*/ 2,
                wrec,
                /*bias*/ 1, dst, last ? out : nullptr, /*tanh*/ 1);
        }
    }
}

// round 6
// speedup vs baseline: 1.9266x; 1.9266x over previous
#include <cuda_runtime.h>
#include <math.h>

#define N_NODES 40000
#define N_EDGES 640000
#define HID     128
#define NH      (N_NODES * HID)
#define NPAD    40960   // padded count array (160 blocks * 256)
#define NSCB    160     // scan blocks

typedef unsigned long long u64;

// ---------------- device scratch (no allocations allowed) ----------------
__device__ __align__(16) float g_xproj[NH];
__device__ __align__(16) float g_stateA[NH];
__device__ __align__(16) float g_stateB[NH];
__device__ __align__(16) float g_aggr[NH];
__device__ __align__(16) float g_wt[HID * HID];
__device__ int   g_rowptr[N_NODES + 1];
__device__ int   g_cursor[N_NODES];
__device__ __align__(16) int g_counts[NPAD];
__device__ int   g_col[N_EDGES];
__device__ int   g_bsum[NSCB];
__device__ int   g_boff[NSCB];
__device__ int   g_is64;

// ---------------- packed f32x2 helpers (B300 FFMA2 path) ----------------
__device__ __forceinline__ void fma2(u64& d, u64 a, u64 b) {
    asm("fma.rn.f32x2 %0, %1, %2, %3;" : "=l"(d) : "l"(a), "l"(b), "l"(d));
}
__device__ __forceinline__ float2 unpack2(u64 v) {
    float2 f; asm("mov.b64 {%0,%1}, %2;" : "=f"(f.x), "=f"(f.y) : "l"(v)); return f;
}

// ---------------- edge dtype probe: int64 vs int32 ----------------
__global__ void detect_kernel(const void* ei) {
    if (threadIdx.x == 0 && blockIdx.x == 0) {
        const long long* p = (const long long*)ei;
        int ok64 = 1;
        for (int i = 0; i < 64; i++) {
            long long v = p[(i * 9973) % 640000];
            if (v < 0 || v >= N_NODES) { ok64 = 0; break; }
        }
        g_is64 = ok64;
    }
}

__device__ __forceinline__ int edge_val(const void* ei, int idx) {
    int v;
    if (g_is64) v = (int)((const long long*)ei)[idx];
    else        v = ((const int*)ei)[idx];
    return ((unsigned)v < N_NODES) ? v : 0;   // clamp: never trap
}

// ---------------- CSR build ----------------
__global__ void zero_counts_kernel() {
    for (int i = blockIdx.x * blockDim.x + threadIdx.x; i < NPAD;
         i += gridDim.x * blockDim.x)
        g_counts[i] = 0;
}

__global__ void hist_kernel(const void* __restrict__ ei) {
    int e = blockIdx.x * blockDim.x + threadIdx.x;
    if (e < N_EDGES) {
        int dst = edge_val(ei, N_EDGES + e);
        atomicAdd(&g_counts[dst], 1);
    }
}

// scan phase A: per-block sums (160 blocks x 256 elements)
__global__ void scan_a_kernel() {
    __shared__ int ws[8];
    int t = threadIdx.x, lane = t & 31, wid = t >> 5;
    int v = g_counts[blockIdx.x * 256 + t];
    int s = v;
    for (int o = 16; o > 0; o >>= 1) s += __shfl_down_sync(0xffffffffu, s, o);
    if (lane == 0) ws[wid] = s;
    __syncthreads();
    if (t == 0) {
        int tot = 0;
        for (int i = 0; i < 8; i++) tot += ws[i];
        g_bsum[blockIdx.x] = tot;
    }
}

// scan phase B: exclusive scan of 160 block sums (1 block, 256 threads)
__global__ void scan_b_kernel() {
    __shared__ int woff[8];
    int t = threadIdx.x, lane = t & 31, wid = t >> 5;
    int v = (t < NSCB) ? g_bsum[t] : 0;
    int p = v;
    for (int o = 1; o < 32; o <<= 1) {
        int n = __shfl_up_sync(0xffffffffu, p, o);
        if (lane >= o) p += n;
    }
    if (lane == 31) woff[wid] = p;
    __syncthreads();
    if (wid == 0) {
        int w = (lane < 8) ? woff[lane] : 0;
        int q = w;
        for (int o = 1; o < 8; o <<= 1) {
            int n = __shfl_up_sync(0xffffffffu, q, o);
            if (lane >= o) q += n;
        }
        if (lane < 8) woff[lane] = q - w;
    }
    __syncthreads();
    if (t < NSCB) g_boff[t] = woff[wid] + (p - v);
}

// scan phase C: local exclusive scan + block offset -> cursor/rowptr
__global__ void scan_c_kernel() {
    __shared__ int woff[8];
    int t = threadIdx.x, lane = t & 31, wid = t >> 5;
    int i = blockIdx.x * 256 + t;
    int v = g_counts[i];
    int p = v;
    for (int o = 1; o < 32; o <<= 1) {
        int n = __shfl_up_sync(0xffffffffu, p, o);
        if (lane >= o) p += n;
    }
    if (lane == 31) woff[wid] = p;
    __syncthreads();
    if (wid == 0) {
        int w = (lane < 8) ? woff[lane] : 0;
        int q = w;
        for (int o = 1; o < 8; o <<= 1) {
            int n = __shfl_up_sync(0xffffffffu, q, o);
            if (lane >= o) q += n;
        }
        if (lane < 8) woff[lane] = q - w;
    }
    __syncthreads();
    int excl = g_boff[blockIdx.x] + woff[wid] + (p - v);
    if (i < N_NODES) {
        g_cursor[i] = excl;
        g_rowptr[i + 1] = excl + v;
    }
    if (i == 0) g_rowptr[0] = 0;
}

__global__ void fill_kernel(const void* __restrict__ ei) {
    int e = blockIdx.x * blockDim.x + threadIdx.x;
    if (e < N_EDGES) {
        int src = edge_val(ei, e);
        int dst = edge_val(ei, N_EDGES + e);
        int pos = atomicAdd(&g_cursor[dst], 1);
        if ((unsigned)pos < N_EDGES) g_col[pos] = src;
    }
}

// ---------------- edge aggregation: warp per node, float4 lanes ----------------
__global__ void __launch_bounds__(256) aggregate_kernel(int src_sel) {
    int node = blockIdx.x * 8 + (threadIdx.x >> 5);
    if (node >= N_NODES) return;
    int lane = threadIdx.x & 31;
    int s = g_rowptr[node];
    int e = g_rowptr[node + 1];
    const float4* st = (const float4*)(src_sel ? g_stateB : g_stateA);
    float4 acc = make_float4(0.f, 0.f, 0.f, 0.f);
    for (int i = s; i < e; i++) {
        float4 v = st[g_col[i] * 32 + lane];
        acc.x += v.x; acc.y += v.y; acc.z += v.z; acc.w += v.w;
    }
    ((float4*)g_aggr)[node * 32 + lane] = acc;
}

// ---------------- transpose 128x128 into g_wt: wt[k][h] = w[h][k] ----------------
__global__ void transpose128_kernel(const float* __restrict__ w) {
    int idx = blockIdx.x * blockDim.x + threadIdx.x;
    if (idx < HID * HID) {
        int h = idx >> 7, k = idx & 127;
        g_wt[k * HID + h] = w[h * HID + k];
    }
}

// ---------------- first state update: stateA = tanh(xproj) ----------------
__global__ void tanh_kernel() {
    int i = blockIdx.x * blockDim.x + threadIdx.x;
    if (i < NH) g_stateA[i] = tanhf(g_xproj[i]);
}

// ---------------- FFMA2 GEMM (conflict-free) ------------------------------------
// dst[r][h] = f(bias? xproj + sum_k A[r][k]*W[k][h])
// 128 threads, 64 rows/block, thread tile 8 rows x 8 cols.
// A row-pairs packed via LDS.128 from k-major sA; W duplicated (w,w) in smem,
// each thread's 64B chunk padded to 80B so LDS.128 reads spread all 8 bank-quads.
#define GR    64
#define KT    16
#define APAD  68            // floats; 68*4=272 B, multiple of 16
#define WPITCH 10           // float2 per (kk, col-group): 8 data + 2 pad = 80 B

// a_sel: 0 = Aext, 1 = g_stateA, 2 = g_aggr
// dst_sel: 0 = g_stateA, 1 = g_stateB, 2 = dst_ext, 3 = g_xproj
__global__ void __launch_bounds__(128, 4) gemm_kernel(
    const float* __restrict__ Aext, int a_sel,
    const float* __restrict__ Wext,
    int use_bias, int dst_sel, float* __restrict__ dst_ext, int do_tanh)
{
    __shared__ float2 sWd[KT * 16 * WPITCH];  // 2560 float2 = 20.5 KB
    __shared__ float  sA[KT * APAD];          // 4.35 KB

    const float* A = (a_sel == 0) ? Aext : ((a_sel == 1) ? g_stateA : g_aggr);
    const float* W = Wext ? Wext : g_wt;
    float* dst = (dst_sel == 0) ? g_stateA :
                 (dst_sel == 1) ? g_stateB :
                 (dst_sel == 2) ? dst_ext  : g_xproj;

    int t = threadIdx.x;                 // 0..127
    int row0 = blockIdx.x * GR;
    int tc = t & 15;                     // col group: cols tc*8 .. +7
    int tg = t >> 4;                     // row group: rows tg*8 .. +7

    u64 acc[4][8];                       // [rowpair][col]
#pragma unroll
    for (int p = 0; p < 4; p++)
#pragma unroll
        for (int j = 0; j < 8; j++) acc[p][j] = 0ull;

    for (int k0 = 0; k0 < HID; k0 += KT) {
        // W tile duplicated: 16 kk x 128 h = 2048 values, 16 per thread
#pragma unroll
        for (int j = 0; j < 16; j++) {
            int idx = t + j * 128;            // 0..2047
            int kk = idx >> 7;
            int h  = idx & 127;
            float wv = W[(k0 + kk) * HID + h];
            sWd[kk * (16 * WPITCH) + (h >> 3) * WPITCH + (h & 7)] = make_float2(wv, wv);
        }
        // A tile transposed: 64 r x 16 k = 256 float4, 2 per thread
#pragma unroll
        for (int j = 0; j < 2; j++) {
            int idx = t + j * 128;            // 0..255
            int r  = idx >> 2;                // 0..63
            int k4 = idx & 3;                 // 0..3
            float4 v = *(const float4*)&A[(row0 + r) * HID + k0 + k4 * 4];
            sA[(k4 * 4 + 0) * APAD + r] = v.x;
            sA[(k4 * 4 + 1) * APAD + r] = v.y;
            sA[(k4 * 4 + 2) * APAD + r] = v.z;
            sA[(k4 * 4 + 3) * APAD + r] = v.w;
        }
        __syncthreads();

#pragma unroll
        for (int kk = 0; kk < KT; kk++) {
            const u64* wp = (const u64*)&sWd[kk * (16 * WPITCH) + tc * WPITCH];
            ulonglong2 w01 = *(const ulonglong2*)(wp + 0);
            ulonglong2 w23 = *(const ulonglong2*)(wp + 2);
            ulonglong2 w45 = *(const ulonglong2*)(wp + 4);
            ulonglong2 w67 = *(const ulonglong2*)(wp + 6);
            const u64* ap = (const u64*)&sA[kk * APAD + tg * 8];
            ulonglong2 a03 = *(const ulonglong2*)(ap + 0);   // rows 0-1, 2-3
            ulonglong2 a47 = *(const ulonglong2*)(ap + 2);   // rows 4-5, 6-7
            u64 wd[8] = {w01.x, w01.y, w23.x, w23.y, w45.x, w45.y, w67.x, w67.y};
            u64 av[4] = {a03.x, a03.y, a47.x, a47.y};
#pragma unroll
            for (int p = 0; p < 4; p++)
#pragma unroll
                for (int j = 0; j < 8; j++) fma2(acc[p][j], av[p], wd[j]);
        }
        __syncthreads();
    }

    // epilogue: pair p holds rows (tg*8+2p) .lo and (tg*8+2p+1) .hi
#pragma unroll
    for (int p = 0; p < 4; p++) {
        float vlo[8], vhi[8];
#pragma unroll
        for (int j = 0; j < 8; j++) {
            float2 q = unpack2(acc[p][j]);
            vlo[j] = q.x; vhi[j] = q.y;
        }
        int rlo = row0 + tg * 8 + 2 * p;
#pragma unroll
        for (int hrow = 0; hrow < 2; hrow++) {
            float* v = hrow ? vhi : vlo;
            int r = rlo + hrow;
            if (use_bias) {
                float4 b0 = *(const float4*)&g_xproj[r * HID + tc * 8];
                float4 b1 = *(const float4*)&g_xproj[r * HID + tc * 8 + 4];
                v[0] += b0.x; v[1] += b0.y; v[2] += b0.z; v[3] += b0.w;
                v[4] += b1.x; v[5] += b1.y; v[6] += b1.z; v[7] += b1.w;
            }
            if (do_tanh) {
#pragma unroll
                for (int j = 0; j < 8; j++) v[j] = tanhf(v[j]);
            }
            *(float4*)&dst[r * HID + tc * 8]     = make_float4(v[0], v[1], v[2], v[3]);
            *(float4*)&dst[r * HID + tc * 8 + 4] = make_float4(v[4], v[5], v[6], v[7]);
        }
    }
}

// ---------------- host orchestration ----------------
extern "C" void kernel_launch(void* const* d_in, const int* in_sizes, int n_in,
                              void* d_out, int out_size)
{
    const void* ei = nullptr;
    const float* x = nullptr;
    const float* w[4] = {nullptr, nullptr, nullptr, nullptr};
    int wn = 0;
    for (int i = 0; i < n_in; i++) {
        if (in_sizes[i] == 2 * N_EDGES)      ei = d_in[i];
        else if (in_sizes[i] == NH)          x  = (const float*)d_in[i];
        else if (in_sizes[i] == HID * HID && wn < 4) w[wn++] = (const float*)d_in[i];
    }
    const float* w_in0  = w[0];
    const float* w_rec0 = w[1];
    const float* w_in1  = w[2];
    const float* w_rec1 = w[3];
    float* out = (float*)d_out;

    // Build dst-major CSR once per launch
    detect_kernel<<<1, 32>>>(ei);
    zero_counts_kernel<<<40, 1024>>>();
    hist_kernel<<<(N_EDGES + 255) / 256, 256>>>(ei);
    scan_a_kernel<<<NSCB, 256>>>();
    scan_b_kernel<<<1, 256>>>();
    scan_c_kernel<<<NSCB, 256>>>();
    fill_kernel<<<(N_EDGES + 255) / 256, 256>>>(ei);

    const int BLOCKS = N_NODES / GR;             // 625
    const int TANH_BLOCKS = (NH + 255) / 256;
    const int AGGR_BLOCKS = (N_NODES + 7) / 8;   // 5000

    for (int layer = 0; layer < 2; layer++) {
        const float* win  = layer ? w_in1  : w_in0;
        const float* wrec = layer ? w_rec1 : w_rec0;

        // xproj = input @ win^T
        transpose128_kernel<<<64, 256>>>(win);
        gemm_kernel<<<BLOCKS, 128>>>(
            layer ? nullptr : x, layer ? 1 : 0,   // A = x or stateA
            nullptr,                              // W = g_wt (transposed)
            0, /*dst=xproj*/ 3, nullptr, 0);

        // state update #1 (initial state zero): stateA = tanh(xproj)
        tanh_kernel<<<TANH_BLOCKS, 256>>>();

        // 8 more updates: state = tanh(xproj + aggr(state) @ wrec)
        for (int it = 0; it < 8; it++) {
            int src = it & 1;            // 0=A,1=B
            aggregate_kernel<<<AGGR_BLOCKS, 256>>>(src);
            int last = (layer == 1 && it == 7);
            int dst = last ? 2 : (1 - src);
            gemm_kernel<<<BLOCKS, 128>>>(
                nullptr, /*A=g_aggr*/ 2,
                wrec,
                /*bias*/ 1, dst, last ? out : nullptr, /*tanh*/ 1);
        }
    }
}

// round 9
// speedup vs baseline: 3.8071x; 1.9761x over previous
#include <cuda_runtime.h>
#include <cuda_bf16.h>
#include <math.h>

#define N_NODES 40000
#define N_EDGES 640000
#define HID     128
#define NH      (N_NODES * HID)
#define NPAD    40960   // padded count array (160 blocks * 256)
#define NSCB    160     // scan blocks

// ---------------- device scratch (no allocations allowed) ----------------
__device__ __align__(16) float g_xproj[NH];
__device__ __align__(16) float g_stateA[NH];
__device__ __align__(16) float g_stateB[NH];
__device__ __align__(16) float g_aggr[NH];
__device__ __align__(16) float g_wt[HID * HID];
__device__ int   g_rowptr[N_NODES + 1];
__device__ int   g_cursor[N_NODES];
__device__ __align__(16) int g_counts[NPAD];
__device__ int   g_col[N_EDGES];
__device__ int   g_bsum[NSCB];
__device__ int   g_boff[NSCB];
__device__ int   g_is64;

// ---------------- bf16 split + mma helpers ----------------
// x = hi + lo with hi = bf16_rn(x), lo = bf16_rn(x - hi); pack pairs into u32
__device__ __forceinline__ void split_pair(float x, float y,
                                           unsigned& hi, unsigned& lo) {
    __nv_bfloat16 hx = __float2bfloat16_rn(x);
    __nv_bfloat16 hy = __float2bfloat16_rn(y);
    __nv_bfloat16 lx = __float2bfloat16_rn(x - __bfloat162float(hx));
    __nv_bfloat16 ly = __float2bfloat16_rn(y - __bfloat162float(hy));
    hi = (unsigned)__bfloat16_as_ushort(hx) |
         ((unsigned)__bfloat16_as_ushort(hy) << 16);
    lo = (unsigned)__bfloat16_as_ushort(lx) |
         ((unsigned)__bfloat16_as_ushort(ly) << 16);
}

__device__ __forceinline__ void mma_bf16(
    float& c0, float& c1, float& c2, float& c3,
    unsigned a0, unsigned a1, unsigned a2, unsigned a3,
    unsigned b0, unsigned b1)
{
    asm("mma.sync.aligned.m16n8k16.row.col.f32.bf16.bf16.f32 "
        "{%0,%1,%2,%3}, {%4,%5,%6,%7}, {%8,%9}, {%0,%1,%2,%3};"
        : "+f"(c0), "+f"(c1), "+f"(c2), "+f"(c3)
        : "r"(a0), "r"(a1), "r"(a2), "r"(a3), "r"(b0), "r"(b1));
}

// ---------------- edge dtype probe: int64 vs int32 ----------------
__global__ void detect_kernel(const void* ei) {
    if (threadIdx.x == 0 && blockIdx.x == 0) {
        const long long* p = (const long long*)ei;
        int ok64 = 1;
        for (int i = 0; i < 64; i++) {
            long long v = p[(i * 9973) % 640000];
            if (v < 0 || v >= N_NODES) { ok64 = 0; break; }
        }
        g_is64 = ok64;
    }
}

__device__ __forceinline__ int edge_val(const void* ei, int idx) {
    int v;
    if (g_is64) v = (int)((const long long*)ei)[idx];
    else        v = ((const int*)ei)[idx];
    return ((unsigned)v < N_NODES) ? v : 0;   // clamp: never trap
}

// ---------------- CSR build ----------------
__global__ void zero_counts_kernel() {
    for (int i = blockIdx.x * blockDim.x + threadIdx.x; i < NPAD;
         i += gridDim.x * blockDim.x)
        g_counts[i] = 0;
}

__global__ void hist_kernel(const void* __restrict__ ei) {
    int e = blockIdx.x * blockDim.x + threadIdx.x;
    if (e < N_EDGES) {
        int dst = edge_val(ei, N_EDGES + e);
        atomicAdd(&g_counts[dst], 1);
    }
}

// scan phase A: per-block sums (160 blocks x 256 elements)
__global__ void scan_a_kernel() {
    __shared__ int ws[8];
    int t = threadIdx.x, lane = t & 31, wid = t >> 5;
    int v = g_counts[blockIdx.x * 256 + t];
    int s = v;
    for (int o = 16; o > 0; o >>= 1) s += __shfl_down_sync(0xffffffffu, s, o);
    if (lane == 0) ws[wid] = s;
    __syncthreads();
    if (t == 0) {
        int tot = 0;
        for (int i = 0; i < 8; i++) tot += ws[i];
        g_bsum[blockIdx.x] = tot;
    }
}

// scan phase B: exclusive scan of 160 block sums
__global__ void scan_b_kernel() {
    __shared__ int woff[8];
    int t = threadIdx.x, lane = t & 31, wid = t >> 5;
    int v = (t < NSCB) ? g_bsum[t] : 0;
    int p = v;
    for (int o = 1; o < 32; o <<= 1) {
        int n = __shfl_up_sync(0xffffffffu, p, o);
        if (lane >= o) p += n;
    }
    if (lane == 31) woff[wid] = p;
    __syncthreads();
    if (wid == 0) {
        int w = (lane < 8) ? woff[lane] : 0;
        int q = w;
        for (int o = 1; o < 8; o <<= 1) {
            int n = __shfl_up_sync(0xffffffffu, q, o);
            if (lane >= o) q += n;
        }
        if (lane < 8) woff[lane] = q - w;
    }
    __syncthreads();
    if (t < NSCB) g_boff[t] = woff[wid] + (p - v);
}

// scan phase C: local exclusive scan + block offset -> cursor/rowptr
__global__ void scan_c_kernel() {
    __shared__ int woff[8];
    int t = threadIdx.x, lane = t & 31, wid = t >> 5;
    int i = blockIdx.x * 256 + t;
    int v = g_counts[i];
    int p = v;
    for (int o = 1; o < 32; o <<= 1) {
        int n = __shfl_up_sync(0xffffffffu, p, o);
        if (lane >= o) p += n;
    }
    if (lane == 31) woff[wid] = p;
    __syncthreads();
    if (wid == 0) {
        int w = (lane < 8) ? woff[lane] : 0;
        int q = w;
        for (int o = 1; o < 8; o <<= 1) {
            int n = __shfl_up_sync(0xffffffffu, q, o);
            if (lane >= o) q += n;
        }
        if (lane < 8) woff[lane] = q - w;
    }
    __syncthreads();
    int excl = g_boff[blockIdx.x] + woff[wid] + (p - v);
    if (i < N_NODES) {
        g_cursor[i] = excl;
        g_rowptr[i + 1] = excl + v;
    }
    if (i == 0) g_rowptr[0] = 0;
}

__global__ void fill_kernel(const void* __restrict__ ei) {
    int e = blockIdx.x * blockDim.x + threadIdx.x;
    if (e < N_EDGES) {
        int src = edge_val(ei, e);
        int dst = edge_val(ei, N_EDGES + e);
        int pos = atomicAdd(&g_cursor[dst], 1);
        if ((unsigned)pos < N_EDGES) g_col[pos] = src;
    }
}

// ---------------- edge aggregation: warp per node, float4 lanes ----------------
__global__ void __launch_bounds__(256) aggregate_kernel(int src_sel) {
    int node = blockIdx.x * 8 + (threadIdx.x >> 5);
    if (node >= N_NODES) return;
    int lane = threadIdx.x & 31;
    int s = g_rowptr[node];
    int e = g_rowptr[node + 1];
    const float4* st = (const float4*)(src_sel ? g_stateB : g_stateA);
    float4 acc = make_float4(0.f, 0.f, 0.f, 0.f);
    for (int i = s; i < e; i++) {
        float4 v = st[g_col[i] * 32 + lane];
        acc.x += v.x; acc.y += v.y; acc.z += v.z; acc.w += v.w;
    }
    ((float4*)g_aggr)[node * 32 + lane] = acc;
}

// ---------------- transpose 128x128: g_wt[a][b] = w[b][a] ----------------
// Turns wrec [k][h] into g_wt [n=h][k] for the n-major GEMM tile loads.
__global__ void transpose128_kernel(const float* __restrict__ w) {
    int idx = blockIdx.x * blockDim.x + threadIdx.x;
    if (idx < HID * HID) {
        int a = idx >> 7, b = idx & 127;
        g_wt[a * HID + b] = w[b * HID + a];
    }
}

// ---------------- first state update: stateA = tanh(xproj) ----------------
__global__ void tanh_kernel() {
    int i = blockIdx.x * blockDim.x + threadIdx.x;
    if (i < NH) g_stateA[i] = tanhf(g_xproj[i]);
}

// ---------------- bf16-split tensor-core GEMM --------------------------------
// dst[m][n] = f((bias? xproj) + sum_k A[m][k] * Wnk[n][k])
// A@W ~= Ahi@Whi + Ahi@Wlo + Alo@Whi  (fp32 accum, mma.m16n8k16.bf16)
// 128 threads (4 warps), block tile 64(m) x 128(n), K tiled by 32.
// warp tile m32 x n64. smem rows pitch 20 u32 (80 B) -> conflict-free frags.
#define GR 64
#define KT 32
#define PU 20    // u32 per row (= 40 bf16)

// a_sel: 0 = Aext, 1 = g_stateA, 2 = g_aggr
// W: Wext if non-null, else g_wt (device-symbol fallback -- NEVER pass g_wt from host!)
// dst_sel: 0 = g_stateA, 1 = g_stateB, 2 = dst_ext, 3 = g_xproj
__global__ void __launch_bounds__(128) gemm_kernel(
    const float* __restrict__ Aext, int a_sel,
    const float* __restrict__ Wext,
    int use_bias, int dst_sel, float* __restrict__ dst_ext, int do_tanh)
{
    __shared__ unsigned sWhi[HID * PU];   // 10.2 KB
    __shared__ unsigned sWlo[HID * PU];   // 10.2 KB
    __shared__ unsigned sAhi[GR * PU];    //  5.1 KB
    __shared__ unsigned sAlo[GR * PU];    //  5.1 KB

    const float* A = (a_sel == 0) ? Aext : ((a_sel == 1) ? g_stateA : g_aggr);
    const float* Wnk = Wext ? Wext : g_wt;
    float* dst = (dst_sel == 0) ? g_stateA :
                 (dst_sel == 1) ? g_stateB :
                 (dst_sel == 2) ? dst_ext  : g_xproj;

    int t = threadIdx.x;
    int lane = t & 31, wid = t >> 5;
    int gid = lane >> 2, tig = lane & 3;
    int wm = wid & 1, wn = wid >> 1;
    int m_w = wm * 32, n_w = wn * 64;
    int row0 = blockIdx.x * GR;

    float acc[2][8][4];
#pragma unroll
    for (int mi = 0; mi < 2; mi++)
#pragma unroll
        for (int ni = 0; ni < 8; ni++)
#pragma unroll
            for (int q = 0; q < 4; q++) acc[mi][ni][q] = 0.f;

    for (int k0 = 0; k0 < HID; k0 += KT) {
        // W chunk: 128 n-rows x 32 k = 1024 float4, 8 per thread
#pragma unroll
        for (int j = 0; j < 8; j++) {
            int idx = t + j * 128;           // 0..1023
            int r = idx >> 3, c4 = idx & 7;
            float4 v = *(const float4*)&Wnk[r * HID + k0 + c4 * 4];
            unsigned h0, l0, h1, l1;
            split_pair(v.x, v.y, h0, l0);
            split_pair(v.z, v.w, h1, l1);
            int s = r * PU + c4 * 2;
            sWhi[s] = h0; sWhi[s + 1] = h1;
            sWlo[s] = l0; sWlo[s + 1] = l1;
        }
        // A chunk: 64 rows x 32 k = 512 float4, 4 per thread
#pragma unroll
        for (int j = 0; j < 4; j++) {
            int idx = t + j * 128;           // 0..511
            int r = idx >> 3, c4 = idx & 7;
            float4 v = *(const float4*)&A[(row0 + r) * HID + k0 + c4 * 4];
            unsigned h0, l0, h1, l1;
            split_pair(v.x, v.y, h0, l0);
            split_pair(v.z, v.w, h1, l1);
            int s = r * PU + c4 * 2;
            sAhi[s] = h0; sAhi[s + 1] = h1;
            sAlo[s] = l0; sAlo[s + 1] = l1;
        }
        __syncthreads();

#pragma unroll
        for (int ks = 0; ks < 2; ks++) {          // two k16 sub-steps
            int ko = ks * 8;                      // u32 offset
            unsigned ah[2][4], al[2][4];
#pragma unroll
            for (int mi = 0; mi < 2; mi++) {
                int ab = (m_w + mi * 16 + gid) * PU + ko + tig;
                ah[mi][0] = sAhi[ab];
                ah[mi][1] = sAhi[ab + 8 * PU];
                ah[mi][2] = sAhi[ab + 4];
                ah[mi][3] = sAhi[ab + 8 * PU + 4];
                al[mi][0] = sAlo[ab];
                al[mi][1] = sAlo[ab + 8 * PU];
                al[mi][2] = sAlo[ab + 4];
                al[mi][3] = sAlo[ab + 8 * PU + 4];
            }
#pragma unroll
            for (int ni = 0; ni < 8; ni++) {
                int bb = (n_w + ni * 8 + gid) * PU + ko + tig;
                unsigned bh0 = sWhi[bb], bh1 = sWhi[bb + 4];
                unsigned bl0 = sWlo[bb], bl1 = sWlo[bb + 4];
#pragma unroll
                for (int mi = 0; mi < 2; mi++) {
                    mma_bf16(acc[mi][ni][0], acc[mi][ni][1],
                             acc[mi][ni][2], acc[mi][ni][3],
                             ah[mi][0], ah[mi][1], ah[mi][2], ah[mi][3],
                             bh0, bh1);
                    mma_bf16(acc[mi][ni][0], acc[mi][ni][1],
                             acc[mi][ni][2], acc[mi][ni][3],
                             ah[mi][0], ah[mi][1], ah[mi][2], ah[mi][3],
                             bl0, bl1);
                    mma_bf16(acc[mi][ni][0], acc[mi][ni][1],
                             acc[mi][ni][2], acc[mi][ni][3],
                             al[mi][0], al[mi][1], al[mi][2], al[mi][3],
                             bh0, bh1);
                }
            }
        }
        __syncthreads();
    }

    // epilogue: c0,c1 -> (row gid, cols 2*tig,+1); c2,c3 -> row gid+8
#pragma unroll
    for (int mi = 0; mi < 2; mi++) {
        int ra = row0 + m_w + mi * 16 + gid;
        int rb = ra + 8;
#pragma unroll
        for (int ni = 0; ni < 8; ni++) {
            int col = n_w + ni * 8 + tig * 2;
            float v0 = acc[mi][ni][0], v1 = acc[mi][ni][1];
            float v2 = acc[mi][ni][2], v3 = acc[mi][ni][3];
            if (use_bias) {
                float2 ba = *(const float2*)&g_xproj[ra * HID + col];
                float2 bb = *(const float2*)&g_xproj[rb * HID + col];
                v0 += ba.x; v1 += ba.y; v2 += bb.x; v3 += bb.y;
            }
            if (do_tanh) {
                v0 = tanhf(v0); v1 = tanhf(v1);
                v2 = tanhf(v2); v3 = tanhf(v3);
            }
            *(float2*)&dst[ra * HID + col] = make_float2(v0, v1);
            *(float2*)&dst[rb * HID + col] = make_float2(v2, v3);
        }
    }
}

// ---------------- host orchestration ----------------
extern "C" void kernel_launch(void* const* d_in, const int* in_sizes, int n_in,
                              void* d_out, int out_size)
{
    const void* ei = nullptr;
    const float* x = nullptr;
    const float* w[4] = {nullptr, nullptr, nullptr, nullptr};
    int wn = 0;
    for (int i = 0; i < n_in; i++) {
        if (in_sizes[i] == 2 * N_EDGES)      ei = d_in[i];
        else if (in_sizes[i] == NH)          x  = (const float*)d_in[i];
        else if (in_sizes[i] == HID * HID && wn < 4) w[wn++] = (const float*)d_in[i];
    }
    const float* w_in0  = w[0];
    const float* w_rec0 = w[1];
    const float* w_in1  = w[2];
    const float* w_rec1 = w[3];
    float* out = (float*)d_out;

    // Build dst-major CSR once per launch
    detect_kernel<<<1, 32>>>(ei);
    zero_counts_kernel<<<40, 1024>>>();
    hist_kernel<<<(N_EDGES + 255) / 256, 256>>>(ei);
    scan_a_kernel<<<NSCB, 256>>>();
    scan_b_kernel<<<1, 256>>>();
    scan_c_kernel<<<NSCB, 256>>>();
    fill_kernel<<<(N_EDGES + 255) / 256, 256>>>(ei);

    const int BLOCKS = N_NODES / GR;             // 625
    const int TANH_BLOCKS = (NH + 255) / 256;
    const int AGGR_BLOCKS = (N_NODES + 7) / 8;   // 5000

    for (int layer = 0; layer < 2; layer++) {
        const float* win  = layer ? w_in1  : w_in0;
        const float* wrec = layer ? w_rec1 : w_rec0;

        // recurrent weight needs [n][k] layout: g_wt[h][k] = wrec[k][h]
        transpose128_kernel<<<64, 256>>>(wrec);

        // xproj = input @ win^T  (win is [h][k] already = Wnk)
        gemm_kernel<<<BLOCKS, 128>>>(
            layer ? nullptr : x, layer ? 1 : 0,
            win, 0, /*dst=xproj*/ 3, nullptr, 0);

        // state update #1 (initial state zero): stateA = tanh(xproj)
        tanh_kernel<<<TANH_BLOCKS, 256>>>();

        // 8 more updates: state = tanh(xproj + aggr(state) @ wrec)
        for (int it = 0; it < 8; it++) {
            int src = it & 1;            // 0=A,1=B
            aggregate_kernel<<<AGGR_BLOCKS, 256>>>(src);
            int last = (layer == 1 && it == 7);
            int dst = last ? 2 : (1 - src);
            gemm_kernel<<<BLOCKS, 128>>>(
                nullptr, /*A=g_aggr*/ 2,
                nullptr /* -> g_wt in-kernel */,
                /*bias*/ 1, dst, last ? out : nullptr, /*tanh*/ 1);
        }
    }
}

// round 10
// speedup vs baseline: 3.8154x; 1.0022x over previous
#include <cuda_runtime.h>
#include <cuda_bf16.h>
#include <math.h>

#define N_NODES 40000
#define N_EDGES 640000
#define HID     128
#define NH      (N_NODES * HID)
#define NPAD    40960   // padded count array (160 blocks * 256)
#define NSCB    160     // scan blocks
#define WPK     64      // u32 per row in presplit arrays (128 k / 2)

// ---------------- device scratch (no allocations allowed) ----------------
__device__ __align__(16) float g_xproj[NH];
__device__ __align__(16) float g_stateA[NH];
__device__ __align__(16) float g_stateB[NH];
__device__ __align__(16) unsigned g_aggrhi[N_NODES * WPK];
__device__ __align__(16) unsigned g_aggrlo[N_NODES * WPK];
__device__ __align__(16) unsigned g_whi[HID * WPK];
__device__ __align__(16) unsigned g_wlo[HID * WPK];
__device__ int   g_rowptr[N_NODES + 1];
__device__ int   g_cursor[N_NODES];
__device__ __align__(16) int g_counts[NPAD];
__device__ int   g_col[N_EDGES];
__device__ int   g_bsum[NSCB];
__device__ int   g_boff[NSCB];
__device__ int   g_is64;

// ---------------- bf16 split + mma helpers ----------------
__device__ __forceinline__ void split_pair(float x, float y,
                                           unsigned& hi, unsigned& lo) {
    __nv_bfloat16 hx = __float2bfloat16_rn(x);
    __nv_bfloat16 hy = __float2bfloat16_rn(y);
    __nv_bfloat16 lx = __float2bfloat16_rn(x - __bfloat162float(hx));
    __nv_bfloat16 ly = __float2bfloat16_rn(y - __bfloat162float(hy));
    hi = (unsigned)__bfloat16_as_ushort(hx) |
         ((unsigned)__bfloat16_as_ushort(hy) << 16);
    lo = (unsigned)__bfloat16_as_ushort(lx) |
         ((unsigned)__bfloat16_as_ushort(ly) << 16);
}

__device__ __forceinline__ void mma_bf16(
    float& c0, float& c1, float& c2, float& c3,
    unsigned a0, unsigned a1, unsigned a2, unsigned a3,
    unsigned b0, unsigned b1)
{
    asm("mma.sync.aligned.m16n8k16.row.col.f32.bf16.bf16.f32 "
        "{%0,%1,%2,%3}, {%4,%5,%6,%7}, {%8,%9}, {%0,%1,%2,%3};"
        : "+f"(c0), "+f"(c1), "+f"(c2), "+f"(c3)
        : "r"(a0), "r"(a1), "r"(a2), "r"(a3), "r"(b0), "r"(b1));
}

// ---------------- edge dtype probe: int64 vs int32 ----------------
__global__ void detect_kernel(const void* ei) {
    if (threadIdx.x == 0 && blockIdx.x == 0) {
        const long long* p = (const long long*)ei;
        int ok64 = 1;
        for (int i = 0; i < 64; i++) {
            long long v = p[(i * 9973) % 640000];
            if (v < 0 || v >= N_NODES) { ok64 = 0; break; }
        }
        g_is64 = ok64;
    }
}

__device__ __forceinline__ int edge_val(const void* ei, int idx) {
    int v;
    if (g_is64) v = (int)((const long long*)ei)[idx];
    else        v = ((const int*)ei)[idx];
    return ((unsigned)v < N_NODES) ? v : 0;   // clamp: never trap
}

// ---------------- weight pre-split: g_whi/g_wlo[n][k2] ----------------
// transpose=0: w is [n][k] (input weights). transpose=1: w is [k][n] (recurrent).
__global__ void split_w_kernel(const float* __restrict__ w, int transpose) {
    int idx = blockIdx.x * blockDim.x + threadIdx.x;   // 0..8191
    if (idx >= HID * WPK) return;
    int n = idx >> 6, k2 = idx & 63;
    int k = k2 * 2;
    float a = transpose ? w[k * HID + n]       : w[n * HID + k];
    float b = transpose ? w[(k + 1) * HID + n] : w[n * HID + k + 1];
    unsigned hi, lo;
    split_pair(a, b, hi, lo);
    g_whi[idx] = hi;
    g_wlo[idx] = lo;
}

// ---------------- CSR build ----------------
__global__ void zero_counts_kernel() {
    for (int i = blockIdx.x * blockDim.x + threadIdx.x; i < NPAD;
         i += gridDim.x * blockDim.x)
        g_counts[i] = 0;
}

__global__ void hist_kernel(const void* __restrict__ ei) {
    int e = blockIdx.x * blockDim.x + threadIdx.x;
    if (e < N_EDGES) {
        int dst = edge_val(ei, N_EDGES + e);
        atomicAdd(&g_counts[dst], 1);
    }
}

// scan phase A: per-block sums
__global__ void scan_a_kernel() {
    __shared__ int ws[8];
    int t = threadIdx.x, lane = t & 31, wid = t >> 5;
    int v = g_counts[blockIdx.x * 256 + t];
    int s = v;
    for (int o = 16; o > 0; o >>= 1) s += __shfl_down_sync(0xffffffffu, s, o);
    if (lane == 0) ws[wid] = s;
    __syncthreads();
    if (t == 0) {
        int tot = 0;
        for (int i = 0; i < 8; i++) tot += ws[i];
        g_bsum[blockIdx.x] = tot;
    }
}

// scan phase B: exclusive scan of block sums
__global__ void scan_b_kernel() {
    __shared__ int woff[8];
    int t = threadIdx.x, lane = t & 31, wid = t >> 5;
    int v = (t < NSCB) ? g_bsum[t] : 0;
    int p = v;
    for (int o = 1; o < 32; o <<= 1) {
        int n = __shfl_up_sync(0xffffffffu, p, o);
        if (lane >= o) p += n;
    }
    if (lane == 31) woff[wid] = p;
    __syncthreads();
    if (wid == 0) {
        int w = (lane < 8) ? woff[lane] : 0;
        int q = w;
        for (int o = 1; o < 8; o <<= 1) {
            int n = __shfl_up_sync(0xffffffffu, q, o);
            if (lane >= o) q += n;
        }
        if (lane < 8) woff[lane] = q - w;
    }
    __syncthreads();
    if (t < NSCB) g_boff[t] = woff[wid] + (p - v);
}

// scan phase C: local scan + offsets
__global__ void scan_c_kernel() {
    __shared__ int woff[8];
    int t = threadIdx.x, lane = t & 31, wid = t >> 5;
    int i = blockIdx.x * 256 + t;
    int v = g_counts[i];
    int p = v;
    for (int o = 1; o < 32; o <<= 1) {
        int n = __shfl_up_sync(0xffffffffu, p, o);
        if (lane >= o) p += n;
    }
    if (lane == 31) woff[wid] = p;
    __syncthreads();
    if (wid == 0) {
        int w = (lane < 8) ? woff[lane] : 0;
        int q = w;
        for (int o = 1; o < 8; o <<= 1) {
            int n = __shfl_up_sync(0xffffffffu, q, o);
            if (lane >= o) q += n;
        }
        if (lane < 8) woff[lane] = q - w;
    }
    __syncthreads();
    int excl = g_boff[blockIdx.x] + woff[wid] + (p - v);
    if (i < N_NODES) {
        g_cursor[i] = excl;
        g_rowptr[i + 1] = excl + v;
    }
    if (i == 0) g_rowptr[0] = 0;
}

__global__ void fill_kernel(const void* __restrict__ ei) {
    int e = blockIdx.x * blockDim.x + threadIdx.x;
    if (e < N_EDGES) {
        int src = edge_val(ei, e);
        int dst = edge_val(ei, N_EDGES + e);
        int pos = atomicAdd(&g_cursor[dst], 1);
        if ((unsigned)pos < N_EDGES) g_col[pos] = src;
    }
}

// ---------------- edge aggregation: warp per node, writes presplit hi/lo ------
__global__ void __launch_bounds__(256) aggregate_kernel(int src_sel) {
    int node = blockIdx.x * 8 + (threadIdx.x >> 5);
    if (node >= N_NODES) return;
    int lane = threadIdx.x & 31;
    int s = g_rowptr[node];
    int e = g_rowptr[node + 1];
    const float4* st = (const float4*)(src_sel ? g_stateB : g_stateA);
    float4 acc = make_float4(0.f, 0.f, 0.f, 0.f);
    for (int i = s; i < e; i++) {
        float4 v = st[g_col[i] * 32 + lane];
        acc.x += v.x; acc.y += v.y; acc.z += v.z; acc.w += v.w;
    }
    unsigned h0, l0, h1, l1;
    split_pair(acc.x, acc.y, h0, l0);
    split_pair(acc.z, acc.w, h1, l1);
    int base = node * WPK + lane * 2;
    *(uint2*)&g_aggrhi[base] = make_uint2(h0, h1);
    *(uint2*)&g_aggrlo[base] = make_uint2(l0, l1);
}

// ---------------- first state update: stateA = tanh(xproj) ----------------
__global__ void tanh_kernel() {
    int i = blockIdx.x * blockDim.x + threadIdx.x;
    if (i < NH) g_stateA[i] = tanhf(g_xproj[i]);
}

// ---------------- bf16-split tensor-core GEMM --------------------------------
// dst[m][n] = f((bias? xproj) + sum_k A[m][k] * W[n][k])
// A@W ~= Ahi@Whi + Ahi@Wlo + Alo@Whi  (fp32 accum, mma.m16n8k16.bf16)
// W always presplit in g_whi/g_wlo. A: fp32 (split in-kernel) or presplit aggr.
// 128 threads (4 warps), block tile 64(m) x 128(n), K tiled by 32.
#define GR 64
#define KT 32
#define PU 20    // u32 per smem row (16 data + 4 pad) -> conflict-free frags

// a_sel: 0 = Aext(fp32), 1 = g_stateA(fp32), 2 = presplit g_aggrhi/lo
// dst_sel: 0 = g_stateA, 1 = g_stateB, 2 = dst_ext, 3 = g_xproj
__global__ void __launch_bounds__(128) gemm_kernel(
    const float* __restrict__ Aext, int a_sel,
    int use_bias, int dst_sel, float* __restrict__ dst_ext, int do_tanh)
{
    __shared__ unsigned sWhi[HID * PU];
    __shared__ unsigned sWlo[HID * PU];
    __shared__ unsigned sAhi[GR * PU];
    __shared__ unsigned sAlo[GR * PU];

    const float* A = (a_sel == 1) ? g_stateA : Aext;
    float* dst = (dst_sel == 0) ? g_stateA :
                 (dst_sel == 1) ? g_stateB :
                 (dst_sel == 2) ? dst_ext  : g_xproj;

    int t = threadIdx.x;
    int lane = t & 31, wid = t >> 5;
    int gid = lane >> 2, tig = lane & 3;
    int wm = wid & 1, wn = wid >> 1;
    int m_w = wm * 32, n_w = wn * 64;
    int row0 = blockIdx.x * GR;

    float acc[2][8][4];
#pragma unroll
    for (int mi = 0; mi < 2; mi++)
#pragma unroll
        for (int ni = 0; ni < 8; ni++)
#pragma unroll
            for (int q = 0; q < 4; q++) acc[mi][ni][q] = 0.f;

    for (int k0 = 0; k0 < HID; k0 += KT) {
        int k20 = k0 >> 1;    // u32 offset of this chunk in presplit rows
        // W tile: 128 rows x 16 u32 = 512 uint4, 4 per thread (hi + lo)
#pragma unroll
        for (int j = 0; j < 4; j++) {
            int idx = t + j * 128;            // 0..511
            int r = idx >> 2, q4 = idx & 3;
            uint4 vh = *(const uint4*)&g_whi[r * WPK + k20 + q4 * 4];
            uint4 vl = *(const uint4*)&g_wlo[r * WPK + k20 + q4 * 4];
            *(uint4*)&sWhi[r * PU + q4 * 4] = vh;
            *(uint4*)&sWlo[r * PU + q4 * 4] = vl;
        }
        // A tile: 64 rows x 16 u32
        if (a_sel == 2) {
            // presplit: 256 uint4 per array, 2 per thread each
#pragma unroll
            for (int j = 0; j < 2; j++) {
                int idx = t + j * 128;        // 0..255
                int r = idx >> 2, q4 = idx & 3;
                uint4 vh = *(const uint4*)&g_aggrhi[(row0 + r) * WPK + k20 + q4 * 4];
                uint4 vl = *(const uint4*)&g_aggrlo[(row0 + r) * WPK + k20 + q4 * 4];
                *(uint4*)&sAhi[r * PU + q4 * 4] = vh;
                *(uint4*)&sAlo[r * PU + q4 * 4] = vl;
            }
        } else {
            // fp32: 512 float4, 4 per thread, split in-kernel
#pragma unroll
            for (int j = 0; j < 4; j++) {
                int idx = t + j * 128;        // 0..511
                int r = idx >> 3, c4 = idx & 7;
                float4 v = *(const float4*)&A[(row0 + r) * HID + k0 + c4 * 4];
                unsigned h0, l0, h1, l1;
                split_pair(v.x, v.y, h0, l0);
                split_pair(v.z, v.w, h1, l1);
                int s = r * PU + c4 * 2;
                sAhi[s] = h0; sAhi[s + 1] = h1;
                sAlo[s] = l0; sAlo[s + 1] = l1;
            }
        }
        __syncthreads();

#pragma unroll
        for (int ks = 0; ks < 2; ks++) {
            int ko = ks * 8;
            unsigned ah[2][4], al[2][4];
#pragma unroll
            for (int mi = 0; mi < 2; mi++) {
                int ab = (m_w + mi * 16 + gid) * PU + ko + tig;
                ah[mi][0] = sAhi[ab];
                ah[mi][1] = sAhi[ab + 8 * PU];
                ah[mi][2] = sAhi[ab + 4];
                ah[mi][3] = sAhi[ab + 8 * PU + 4];
                al[mi][0] = sAlo[ab];
                al[mi][1] = sAlo[ab + 8 * PU];
                al[mi][2] = sAlo[ab + 4];
                al[mi][3] = sAlo[ab + 8 * PU + 4];
            }
#pragma unroll
            for (int ni = 0; ni < 8; ni++) {
                int bb = (n_w + ni * 8 + gid) * PU + ko + tig;
                unsigned bh0 = sWhi[bb], bh1 = sWhi[bb + 4];
                unsigned bl0 = sWlo[bb], bl1 = sWlo[bb + 4];
#pragma unroll
                for (int mi = 0; mi < 2; mi++) {
                    mma_bf16(acc[mi][ni][0], acc[mi][ni][1],
                             acc[mi][ni][2], acc[mi][ni][3],
                             ah[mi][0], ah[mi][1], ah[mi][2], ah[mi][3],
                             bh0, bh1);
                    mma_bf16(acc[mi][ni][0], acc[mi][ni][1],
                             acc[mi][ni][2], acc[mi][ni][3],
                             ah[mi][0], ah[mi][1], ah[mi][2], ah[mi][3],
                             bl0, bl1);
                    mma_bf16(acc[mi][ni][0], acc[mi][ni][1],
                             acc[mi][ni][2], acc[mi][ni][3],
                             al[mi][0], al[mi][1], al[mi][2], al[mi][3],
                             bh0, bh1);
                }
            }
        }
        __syncthreads();
    }

#pragma unroll
    for (int mi = 0; mi < 2; mi++) {
        int ra = row0 + m_w + mi * 16 + gid;
        int rb = ra + 8;
#pragma unroll
        for (int ni = 0; ni < 8; ni++) {
            int col = n_w + ni * 8 + tig * 2;
            float v0 = acc[mi][ni][0], v1 = acc[mi][ni][1];
            float v2 = acc[mi][ni][2], v3 = acc[mi][ni][3];
            if (use_bias) {
                float2 ba = *(const float2*)&g_xproj[ra * HID + col];
                float2 bb = *(const float2*)&g_xproj[rb * HID + col];
                v0 += ba.x; v1 += ba.y; v2 += bb.x; v3 += bb.y;
            }
            if (do_tanh) {
                v0 = tanhf(v0); v1 = tanhf(v1);
                v2 = tanhf(v2); v3 = tanhf(v3);
            }
            *(float2*)&dst[ra * HID + col] = make_float2(v0, v1);
            *(float2*)&dst[rb * HID + col] = make_float2(v2, v3);
        }
    }
}

// ---------------- host orchestration ----------------
extern "C" void kernel_launch(void* const* d_in, const int* in_sizes, int n_in,
                              void* d_out, int out_size)
{
    const void* ei = nullptr;
    const float* x = nullptr;
    const float* w[4] = {nullptr, nullptr, nullptr, nullptr};
    int wn = 0;
    for (int i = 0; i < n_in; i++) {
        if (in_sizes[i] == 2 * N_EDGES)      ei = d_in[i];
        else if (in_sizes[i] == NH)          x  = (const float*)d_in[i];
        else if (in_sizes[i] == HID * HID && wn < 4) w[wn++] = (const float*)d_in[i];
    }
    const float* w_in0  = w[0];
    const float* w_rec0 = w[1];
    const float* w_in1  = w[2];
    const float* w_rec1 = w[3];
    float* out = (float*)d_out;

    const int BLOCKS = N_NODES / GR;             // 625
    const int TANH_BLOCKS = (NH + 255) / 256;
    const int AGGR_BLOCKS = (N_NODES + 7) / 8;   // 5000
    const int SPLITW_BLOCKS = (HID * WPK + 255) / 256;  // 32

    // order chosen so launch idx 3 = gemm_kernel (the one ncu profiles)
    detect_kernel<<<1, 32>>>(ei);                            // 0
    zero_counts_kernel<<<40, 1024>>>();                      // 1
    split_w_kernel<<<SPLITW_BLOCKS, 256>>>(w_in0, 0);        // 2
    gemm_kernel<<<BLOCKS, 128>>>(x, 0, 0, 3, nullptr, 0);    // 3: xproj = x @ win0^T
    hist_kernel<<<(N_EDGES + 255) / 256, 256>>>(ei);         // 4
    scan_a_kernel<<<NSCB, 256>>>();
    scan_b_kernel<<<1, 256>>>();
    scan_c_kernel<<<NSCB, 256>>>();
    fill_kernel<<<(N_EDGES + 255) / 256, 256>>>(ei);
    tanh_kernel<<<TANH_BLOCKS, 256>>>();                     // stateA = tanh(xproj)

    for (int layer = 0; layer < 2; layer++) {
        if (layer == 1) {
            // layer-1 projection: xproj = stateA @ win1^T, then tanh
            split_w_kernel<<<SPLITW_BLOCKS, 256>>>(w_in1, 0);
            gemm_kernel<<<BLOCKS, 128>>>(nullptr, 1, 0, 3, nullptr, 0);
            tanh_kernel<<<TANH_BLOCKS, 256>>>();
        }
        const float* wrec = layer ? w_rec1 : w_rec0;
        split_w_kernel<<<SPLITW_BLOCKS, 256>>>(wrec, 1);

        for (int it = 0; it < 8; it++) {
            int src = it & 1;            // 0=A,1=B
            aggregate_kernel<<<AGGR_BLOCKS, 256>>>(src);
            int last = (layer == 1 && it == 7);
            int dst = last ? 2 : (1 - src);
            gemm_kernel<<<BLOCKS, 128>>>(
                nullptr, /*A=presplit aggr*/ 2,
                /*bias*/ 1, dst, last ? out : nullptr, /*tanh*/ 1);
        }
    }
}